// round 15
// baseline (speedup 1.0000x reference)
#include <cuda_runtime.h>
#include <cuda_fp16.h>
#include <math.h>
#include <stdint.h>

// Problem constants
#define BATCH 32
#define SEQ   128
#define WL    20
#define D     300
#define DPAD  320
#define M_SEQ (BATCH*SEQ*WL)      // 81920
#define M_VEC (BATCH*SEQ)         // 4096
#define NEG_INF -1000000000.0f

// Scratch (__device__ globals — no cudaMalloc allowed)
// +64 pad: score epilogue reads vecpart rows with o up to 319.
__device__ float g_vecpart[M_VEC * D + 64];
__device__ float g_score[M_SEQ];
__device__ __align__(16) __half g_Ws[DPAD * DPAD];
__device__ __align__(16) __half g_Wv[DPAD * DPAD];
__device__ __align__(16) __half g_seqh[(size_t)M_SEQ * DPAD];   // cols 0..299 valid
__device__ __align__(16) __half g_vech[(size_t)M_VEC * DPAD];

// ---------------------------------------------------------------------------
// PTX helpers (sm_80-era — valid at plain sm_103 target)
// ---------------------------------------------------------------------------
__device__ __forceinline__ uint32_t smem_u32(const void* p) {
    uint32_t a;
    asm("{ .reg .u64 t; cvta.to.shared.u64 t, %1; cvt.u32.u64 %0, t; }" : "=r"(a) : "l"(p));
    return a;
}
__device__ __forceinline__ void ldsm_x4(uint32_t* r, uint32_t addr) {
    asm volatile("ldmatrix.sync.aligned.m8n8.x4.shared.b16 {%0,%1,%2,%3}, [%4];"
                 : "=r"(r[0]), "=r"(r[1]), "=r"(r[2]), "=r"(r[3]) : "r"(addr));
}
__device__ __forceinline__ void mma_f16(float* c, const uint32_t* a, const uint32_t* b) {
    asm volatile("mma.sync.aligned.m16n8k16.row.col.f32.f16.f16.f32 "
                 "{%0,%1,%2,%3}, {%4,%5,%6,%7}, {%8,%9}, {%0,%1,%2,%3};"
                 : "+f"(c[0]), "+f"(c[1]), "+f"(c[2]), "+f"(c[3])
                 : "r"(a[0]), "r"(a[1]), "r"(a[2]), "r"(a[3]), "r"(b[0]), "r"(b[1]));
}
__device__ __forceinline__ void cp_async16(uint32_t dst, const void* src) {
    asm volatile("cp.async.cg.shared.global [%0], [%1], 16;"
                 :: "r"(dst), "l"((size_t)__cvta_generic_to_global(src)) : "memory");
}
#define CP_COMMIT() asm volatile("cp.async.commit_group;" ::: "memory")
#define CP_WAIT0()  asm volatile("cp.async.wait_group 0;" ::: "memory")

__device__ __forceinline__ float tanh_fast(float x) {
    float y;
    asm("tanh.approx.f32 %0, %1;" : "=f"(y) : "f"(x));
    return y;
}

// ---------------------------------------------------------------------------
// Prep kernels (vec + W only — seq conversion is fused into score)
// ---------------------------------------------------------------------------
__device__ __forceinline__ void cvt8_store(__half* dst, const float* src, int k8) {
    uint4 out;
    __half2 h[4];
    if (k8 < 37) {
        float4 a = *(const float4*)(src);
        float4 b = *(const float4*)(src + 4);
        h[0] = __floats2half2_rn(a.x, a.y);
        h[1] = __floats2half2_rn(a.z, a.w);
        h[2] = __floats2half2_rn(b.x, b.y);
        h[3] = __floats2half2_rn(b.z, b.w);
    } else if (k8 == 37) {
        float4 a = *(const float4*)(src);
        h[0] = __floats2half2_rn(a.x, a.y);
        h[1] = __floats2half2_rn(a.z, a.w);
        h[2] = __floats2half2_rn(0.f, 0.f);
        h[3] = h[2];
    } else {
        h[0] = __floats2half2_rn(0.f, 0.f);
        h[1] = h[0]; h[2] = h[0]; h[3] = h[0];
    }
    memcpy(&out, h, 16);
    *(uint4*)dst = out;
}

__global__ __launch_bounds__(256)
void prep_vec_kernel(const float* __restrict__ vec)
{
    size_t gid = (size_t)blockIdx.x * 256 + threadIdx.x;
    if (gid >= (size_t)M_VEC * (DPAD / 8)) return;
    size_t row = gid / (DPAD / 8);
    int k8 = (int)(gid % (DPAD / 8));
    cvt8_store(g_vech + row * DPAD + k8 * 8, vec + row * D + (size_t)k8 * 8, k8);
}

__global__ __launch_bounds__(256)
void prep_w_kernel(const float* __restrict__ W)
{
    int idx = blockIdx.x * 256 + threadIdx.x;
    if (idx >= DPAD * DPAD) return;
    int o = idx / DPAD, k = idx - o * DPAD;
    float ws = 0.f, wv = 0.f;
    if (o < D && k < D) {
        ws = W[(size_t)o * 600 + k];
        wv = W[(size_t)o * 600 + 300 + k];
    }
    g_Ws[idx] = __float2half_rn(ws);
    g_Wv[idx] = __float2half_rn(wv);
}

// ---------------------------------------------------------------------------
// score kernel: m-tile 128, fp32 seq converted inline (coalesced linear
// staging) into resident fp16 A chunks; also writes g_seqh for softmax.
// 5 o-parts x 5 k-chunks, double-buffered 64x64 B via cp.async.
// 4 warps (128 threads), warp tile m32 x n64. smem 111872 (2 CTAs/SM).
// ---------------------------------------------------------------------------
#define ACHUNK (128 * 144)               // 18432
#define SM_A 0
#define SM_B (5 * ACHUNK)                // 92160
#define SVS  (SM_B + 2 * 9216)           // 110592
#define SMEM_SCORE (SVS + 320 * 4)       // 111872

__device__ __forceinline__ void stage_B(uint32_t sb, int buf, int ot, int kc)
{
    const int tid = threadIdx.x;
    const uint32_t base = sb + SM_B + (uint32_t)buf * 9216;
#pragma unroll
    for (int q = 0; q < 4; q++) {        // 512 segs / 128 thr
        int it = tid + q * 128;
        int r = it >> 3, s = it & 7;
        cp_async16(base + (uint32_t)(r * 144 + s * 16),
                   g_Ws + (size_t)(ot * 64 + r) * DPAD + kc * 64 + s * 8);
    }
    CP_COMMIT();
}

__global__ __launch_bounds__(128, 2)
void score_mma_kernel(const float* __restrict__ seq,
                      const float* __restrict__ v)
{
    extern __shared__ char smem[];
    const uint32_t sb = smem_u32(smem);
    const int tid = threadIdx.x;
    const int wid = tid >> 5, lid = tid & 31;
    const int m0 = blockIdx.x * 128;
    const int wm = wid * 32;

    float* vsm = (float*)(smem + SVS);   // [320], zero-padded

    // Kick B(0,0) prefetch first so it overlaps the A conversion below.
    stage_B(sb, 0, 0, 0);

    // --- Fused A staging: coalesced linear fp32 read, convert, STS + STG ---
    // CTA block = 128 rows x 300 floats contiguous = 9600 float4.
    {
        const float4* src4 = (const float4*)(seq + (size_t)m0 * D);
        __half* gdst = g_seqh + (size_t)m0 * DPAD;
        for (int idx = tid; idx < 9600; idx += 128) {
            int row = idx / 75;
            int col4 = (idx - row * 75) * 4;     // 0..296, never crosses row
            float4 x = src4[idx];
            __half2 h0 = __floats2half2_rn(x.x, x.y);
            __half2 h1 = __floats2half2_rn(x.z, x.w);
            uint2 pk;
            memcpy(&pk, &h0, 4);
            memcpy(((char*)&pk) + 4, &h1, 4);
            int kc = col4 >> 6, off = col4 & 63;
            *(uint2*)(smem + SM_A + kc * ACHUNK + row * 144 + off * 2) = pk;
            *(uint2*)(gdst + (size_t)row * DPAD + col4) = pk;
        }
        // Zero-pad k = 300..319 in chunk 4 (one row per thread)
        {
            const int row = tid;                 // 128 threads = 128 rows
            uint32_t base = sb + SM_A + 4 * ACHUNK + (uint32_t)row * 144 + 88;
            uint2 z = make_uint2(0u, 0u);
#pragma unroll
            for (int q = 0; q < 5; q++)
                *(uint2*)((char*)smem + (base - sb) + q * 8) = z;
        }
    }

    for (int it = tid; it < 320; it += 128)
        vsm[it] = (it < D) ? v[it] : 0.f;

    CP_WAIT0();
    __syncthreads();

    // ldmatrix lane addressing
    const int a_row = ((lid >> 3) & 1) * 8 + (lid & 7);
    const int a_col = (lid >> 4) * 8;
    const int b_row = (lid >> 4) * 8 + (lid & 7);
    const int b_col = ((lid >> 3) & 1) * 8;
    const uint32_t aAoff = (uint32_t)((wm + a_row) * 144 + a_col * 2);
    const uint32_t aBoff = (uint32_t)(b_row * 144 + b_col * 2);

    const int g = lid >> 2, t = lid & 3;
    int rr[4];
    rr[0] = wm + g;      rr[1] = wm + 8 + g;
    rr[2] = wm + 16 + g; rr[3] = wm + 24 + g;
    const float* vp[4];
#pragma unroll
    for (int q = 0; q < 4; q++)
        vp[q] = g_vecpart + (size_t)((m0 + rr[q]) / WL) * D;

    float p[4] = {0.f, 0.f, 0.f, 0.f};
    float acc0[8][4], acc1[8][4];

    for (int i = 0; i < 25; i++) {
        const int ot = i / 5, kc = i - ot * 5, buf = i & 1;

        if (kc == 0) {
#pragma unroll
            for (int j = 0; j < 8; j++)
#pragma unroll
                for (int q = 0; q < 4; q++) { acc0[j][q] = 0.f; acc1[j][q] = 0.f; }
        }

        if (i + 1 < 25) {
            int ni = i + 1, not_ = ni / 5, nkc = ni - not_ * 5;
            stage_B(sb, ni & 1, not_, nkc);
        }

        const uint32_t abase = sb + SM_A + (uint32_t)kc * ACHUNK;
        const uint32_t bbase = sb + SM_B + (uint32_t)buf * 9216;
#pragma unroll
        for (int ks = 0; ks < 4; ks++) {
            const uint32_t kb = (uint32_t)ks * 32;
            uint32_t a0[4], a1[4];
            ldsm_x4(a0, abase + aAoff + kb);
            ldsm_x4(a1, abase + aAoff + kb + 16 * 144);
#pragma unroll
            for (int pp = 0; pp < 4; pp++) {
                uint32_t b[4];
                ldsm_x4(b, bbase + aBoff + kb + (uint32_t)(pp * 16 * 144));
                mma_f16(acc0[2*pp],   a0, b);
                mma_f16(acc0[2*pp+1], a0, b + 2);
                mma_f16(acc1[2*pp],   a1, b);
                mma_f16(acc1[2*pp+1], a1, b + 2);
            }
        }

        // End of o-part: tanh(lin)*v (branch-free: padded o terms are 0)
        if (kc == 4) {
            const int o0 = ot * 64;
#pragma unroll
            for (int j = 0; j < 8; j++) {
                int o = o0 + j * 8 + 2 * t;
                float v0 = vsm[o], v1 = vsm[o + 1];
                p[0] += tanh_fast(acc0[j][0] + __ldg(vp[0] + o)) * v0
                      + tanh_fast(acc0[j][1] + __ldg(vp[0] + o + 1)) * v1;
                p[1] += tanh_fast(acc0[j][2] + __ldg(vp[1] + o)) * v0
                      + tanh_fast(acc0[j][3] + __ldg(vp[1] + o + 1)) * v1;
                p[2] += tanh_fast(acc1[j][0] + __ldg(vp[2] + o)) * v0
                      + tanh_fast(acc1[j][1] + __ldg(vp[2] + o + 1)) * v1;
                p[3] += tanh_fast(acc1[j][2] + __ldg(vp[3] + o)) * v0
                      + tanh_fast(acc1[j][3] + __ldg(vp[3] + o + 1)) * v1;
            }
        }

        CP_WAIT0();
        __syncthreads();
    }

#pragma unroll
    for (int q = 0; q < 4; q++) {
        p[q] += __shfl_xor_sync(0xffffffffu, p[q], 1);
        p[q] += __shfl_xor_sync(0xffffffffu, p[q], 2);
    }
    if (t == 0) {
#pragma unroll
        for (int q = 0; q < 4; q++)
            g_score[m0 + rr[q]] = p[q];
    }
}

// ---------------------------------------------------------------------------
// vecpart via fp16 HMMA, single-stage (unchanged from R11/R14).
// grid = (64, 5): m-tiles of 64, 4 warps (m16). smem 92416 -> 2 CTAs/SM.
// ---------------------------------------------------------------------------
#define VCHUNK (64 * 144)                // 9216
#define VSM_A 0                          // 5 chunks = 46080
#define VSM_B (5 * VCHUNK)               // 46080
#define VSM_BIAS (2 * 5 * VCHUNK)        // 92160
#define SMEM_VECP (VSM_BIAS + 256)       // 92416

__global__ __launch_bounds__(128, 2)
void vecpart_mma_kernel(const float* __restrict__ bias)
{
    extern __shared__ char smem[];
    const uint32_t sb = smem_u32(smem);
    const int tid = threadIdx.x;
    const int wid = tid >> 5, lid = tid & 31;
    const int m0 = blockIdx.x * 64;
    const int o0 = blockIdx.y * 64;
    const int wm = wid * 16;

    float* bsm = (float*)(smem + VSM_BIAS);

#pragma unroll
    for (int q = 0; q < 20; q++) {
        int it = tid + q * 128;
        int kc = it >> 9;
        int w = it & 511;
        int r = w >> 3, s = w & 7;
        cp_async16(sb + VSM_A + (uint32_t)(kc * VCHUNK + r * 144 + s * 16),
                   g_vech + (size_t)(m0 + r) * DPAD + kc * 64 + s * 8);
        cp_async16(sb + VSM_B + (uint32_t)(kc * VCHUNK + r * 144 + s * 16),
                   g_Wv + (size_t)(o0 + r) * DPAD + kc * 64 + s * 8);
    }
    CP_COMMIT();

    if (tid < 64) bsm[tid] = (o0 + tid < D) ? bias[o0 + tid] : 0.f;

    CP_WAIT0();
    __syncthreads();

    const int a_row = ((lid >> 3) & 1) * 8 + (lid & 7);
    const int a_col = (lid >> 4) * 8;
    const int b_row = (lid >> 4) * 8 + (lid & 7);
    const int b_col = ((lid >> 3) & 1) * 8;
    const uint32_t aAoff = (uint32_t)((wm + a_row) * 144 + a_col * 2);
    const uint32_t aBoff = (uint32_t)(b_row * 144 + b_col * 2);

    const int g = lid >> 2, t = lid & 3;
    const int r0 = wm + g, r1 = wm + 8 + g;

    float acc[8][4];
#pragma unroll
    for (int j = 0; j < 8; j++)
#pragma unroll
        for (int q = 0; q < 4; q++) acc[j][q] = 0.f;

#pragma unroll
    for (int kc = 0; kc < 5; kc++) {
        const uint32_t abase = sb + VSM_A + (uint32_t)kc * VCHUNK;
        const uint32_t bbase = sb + VSM_B + (uint32_t)kc * VCHUNK;
#pragma unroll
        for (int ks = 0; ks < 4; ks++) {
            const uint32_t kb = (uint32_t)ks * 32;
            uint32_t a0[4];
            ldsm_x4(a0, abase + aAoff + kb);
#pragma unroll
            for (int pp = 0; pp < 4; pp++) {
                uint32_t b[4];
                ldsm_x4(b, bbase + aBoff + kb + (uint32_t)(pp * 16 * 144));
                mma_f16(acc[2*pp],   a0, b);
                mma_f16(acc[2*pp+1], a0, b + 2);
            }
        }
    }

#pragma unroll
    for (int j = 0; j < 8; j++) {
        int oc = j * 8 + 2 * t;
        int o = o0 + oc;
        if (o < D) {
            float bb = bsm[oc];
            g_vecpart[(size_t)(m0 + r0) * D + o] = acc[j][0] + bb;
            g_vecpart[(size_t)(m0 + r1) * D + o] = acc[j][2] + bb;
        }
        if (o + 1 < D) {
            float bb = bsm[oc + 1];
            g_vecpart[(size_t)(m0 + r0) * D + o + 1] = acc[j][1] + bb;
            g_vecpart[(size_t)(m0 + r1) * D + o + 1] = acc[j][3] + bb;
        }
    }
}

// ---------------------------------------------------------------------------
// softmax+weighted: ONE WARP per (b,s), fp16 seq (g_seqh). (unchanged R14)
// ---------------------------------------------------------------------------
__global__ __launch_bounds__(256)
void softmax_weighted_kernel(const int* __restrict__ masks,
                             float* __restrict__ out)
{
    const int warp = threadIdx.x >> 5, lid = threadIdx.x & 31;
    const int bs = blockIdx.x * 8 + warp;

    float s = -1e30f;
    if (lid < WL) {
        s = g_score[bs * WL + lid];
        if (masks[bs * WL + lid] == 0) s = NEG_INF;
    }
    float mx = s;
#pragma unroll
    for (int off = 16; off > 0; off >>= 1)
        mx = fmaxf(mx, __shfl_xor_sync(0xffffffffu, mx, off));
    float e = (lid < WL) ? expf(s - mx) : 0.f;
    float sum = e;
#pragma unroll
    for (int off = 16; off > 0; off >>= 1)
        sum += __shfl_xor_sync(0xffffffffu, sum, off);
    const float inv = 1.f / sum;

    float al[WL];
#pragma unroll
    for (int w = 0; w < WL; w++)
        al[w] = __shfl_sync(0xffffffffu, e, w) * inv;

    const __half* base = g_seqh + (size_t)bs * WL * DPAD;
    float* obase = out + (size_t)bs * D;
    for (int d2 = lid; d2 < D / 2; d2 += 32) {
        float a0 = 0.f, a1 = 0.f;
#pragma unroll
        for (int w = 0; w < WL; w++) {
            float2 x = __half22float2(*(const __half2*)(base + w * DPAD + d2 * 2));
            a0 += al[w] * x.x;
            a1 += al[w] * x.y;
        }
        obase[d2 * 2]     = a0;
        obase[d2 * 2 + 1] = a1;
    }
}

// ---------------------------------------------------------------------------
extern "C" void kernel_launch(void* const* d_in, const int* in_sizes, int n_in,
                              void* d_out, int out_size)
{
    const float* seq   = (const float*)d_in[0];
    const float* vec   = (const float*)d_in[1];
    const int*   masks = (const int*)  d_in[2];
    const float* W     = (const float*)d_in[3];
    const float* bias  = (const float*)d_in[4];
    const float* v     = (const float*)d_in[5];
    float* out = (float*)d_out;

    cudaFuncSetAttribute(score_mma_kernel,
                         cudaFuncAttributeMaxDynamicSharedMemorySize, SMEM_SCORE);
    cudaFuncSetAttribute(vecpart_mma_kernel,
                         cudaFuncAttributeMaxDynamicSharedMemorySize, SMEM_VECP);

    prep_w_kernel<<<(DPAD * DPAD + 255) / 256, 256>>>(W);
    prep_vec_kernel<<<(int)(((size_t)M_VEC * (DPAD / 8) + 255) / 256), 256>>>(vec);
    vecpart_mma_kernel<<<dim3(M_VEC / 64, 5), 128, SMEM_VECP>>>(bias);
    score_mma_kernel<<<M_SEQ / 128, 128, SMEM_SCORE>>>(seq, v);
    softmax_weighted_kernel<<<M_VEC / 8, 256>>>(masks, out);
}

// round 16
// speedup vs baseline: 1.1014x; 1.1014x over previous
#include <cuda_runtime.h>
#include <cuda_fp16.h>
#include <math.h>
#include <stdint.h>

// Problem constants
#define BATCH 32
#define SEQ   128
#define WL    20
#define D     300
#define DPAD  320
#define M_SEQ (BATCH*SEQ*WL)      // 81920
#define M_VEC (BATCH*SEQ)         // 4096
#define NEG_INF -1000000000.0f

// Scratch (__device__ globals — no cudaMalloc allowed)
// +64 pad: score epilogue reads vecpart rows with o up to 319.
__device__ float g_vecpart[M_VEC * D + 64];
__device__ float g_score[M_SEQ];
__device__ __align__(16) __half g_Ws[DPAD * DPAD];
__device__ __align__(16) __half g_Wv[DPAD * DPAD];
__device__ __align__(16) __half g_seqh[(size_t)M_SEQ * DPAD];
__device__ __align__(16) __half g_vech[(size_t)M_VEC * DPAD];

// ---------------------------------------------------------------------------
// PTX helpers (sm_80-era — valid at plain sm_103 target)
// ---------------------------------------------------------------------------
__device__ __forceinline__ uint32_t smem_u32(const void* p) {
    uint32_t a;
    asm("{ .reg .u64 t; cvta.to.shared.u64 t, %1; cvt.u32.u64 %0, t; }" : "=r"(a) : "l"(p));
    return a;
}
__device__ __forceinline__ void ldsm_x4(uint32_t* r, uint32_t addr) {
    asm volatile("ldmatrix.sync.aligned.m8n8.x4.shared.b16 {%0,%1,%2,%3}, [%4];"
                 : "=r"(r[0]), "=r"(r[1]), "=r"(r[2]), "=r"(r[3]) : "r"(addr));
}
__device__ __forceinline__ void mma_f16(float* c, const uint32_t* a, const uint32_t* b) {
    asm volatile("mma.sync.aligned.m16n8k16.row.col.f32.f16.f16.f32 "
                 "{%0,%1,%2,%3}, {%4,%5,%6,%7}, {%8,%9}, {%0,%1,%2,%3};"
                 : "+f"(c[0]), "+f"(c[1]), "+f"(c[2]), "+f"(c[3])
                 : "r"(a[0]), "r"(a[1]), "r"(a[2]), "r"(a[3]), "r"(b[0]), "r"(b[1]));
}
__device__ __forceinline__ void cp_async16(uint32_t dst, const void* src) {
    asm volatile("cp.async.cg.shared.global [%0], [%1], 16;"
                 :: "r"(dst), "l"((size_t)__cvta_generic_to_global(src)) : "memory");
}
#define CP_COMMIT() asm volatile("cp.async.commit_group;" ::: "memory")
#define CP_WAIT0()  asm volatile("cp.async.wait_group 0;" ::: "memory")

__device__ __forceinline__ float tanh_fast(float x) {
    float y;
    asm("tanh.approx.f32 %0, %1;" : "=f"(y) : "f"(x));
    return y;
}

// ---------------------------------------------------------------------------
// Prep kernels: fp16 conversion, 8 threads/row (shift/mask), branch-free
// fast path for the 7 fully-in-bounds parts; tail logic only in part 7.
// ---------------------------------------------------------------------------
__device__ __forceinline__ void cvt8_full(__half* dst, const float* src) {
    float4 a = *(const float4*)(src);
    float4 b = *(const float4*)(src + 4);
    __half2 h[4];
    h[0] = __floats2half2_rn(a.x, a.y);
    h[1] = __floats2half2_rn(a.z, a.w);
    h[2] = __floats2half2_rn(b.x, b.y);
    h[3] = __floats2half2_rn(b.z, b.w);
    uint4 out;
    memcpy(&out, h, 16);
    *(uint4*)dst = out;
}

__device__ __forceinline__ void cvt_row_part(__half* dst, const float* src, int part) {
    if (part < 7) {
        // k8 = part*5 .. part*5+4, all <= 34 < 37: straight-line
        const float* s = src + part * 40;
        __half* d = dst + part * 40;
#pragma unroll
        for (int q = 0; q < 5; q++)
            cvt8_full(d + q * 8, s + q * 8);
    } else {
        // k8 = 35, 36 full; 37 partial (296..299); 38, 39 zero
        cvt8_full(dst + 280, src + 280);
        cvt8_full(dst + 288, src + 288);
        {
            float4 a = *(const float4*)(src + 296);
            __half2 h[4];
            h[0] = __floats2half2_rn(a.x, a.y);
            h[1] = __floats2half2_rn(a.z, a.w);
            h[2] = __floats2half2_rn(0.f, 0.f);
            h[3] = h[2];
            uint4 out;
            memcpy(&out, h, 16);
            *(uint4*)(dst + 296) = out;
        }
        uint4 z = make_uint4(0u, 0u, 0u, 0u);
        *(uint4*)(dst + 304) = z;
        *(uint4*)(dst + 312) = z;
    }
}

__global__ __launch_bounds__(256)
void prep_seq_kernel(const float* __restrict__ seq)
{
    uint32_t gid = blockIdx.x * 256 + threadIdx.x;   // < M_SEQ*8
    uint32_t row = gid >> 3, part = gid & 7;
    cvt_row_part(g_seqh + (size_t)row * DPAD, seq + (size_t)row * D, part);
}

__global__ __launch_bounds__(256)
void prep_vec_kernel(const float* __restrict__ vec)
{
    uint32_t gid = blockIdx.x * 256 + threadIdx.x;   // < M_VEC*8
    uint32_t row = gid >> 3, part = gid & 7;
    cvt_row_part(g_vech + (size_t)row * DPAD, vec + (size_t)row * D, part);
}

__global__ __launch_bounds__(256)
void prep_w_kernel(const float* __restrict__ W)
{
    int idx = blockIdx.x * 256 + threadIdx.x;
    if (idx >= DPAD * DPAD) return;
    int o = idx / DPAD, k = idx - o * DPAD;
    float ws = 0.f, wv = 0.f;
    if (o < D && k < D) {
        ws = W[(size_t)o * 600 + k];
        wv = W[(size_t)o * 600 + 300 + k];
    }
    g_Ws[idx] = __float2half_rn(ws);
    g_Wv[idx] = __float2half_rn(wv);
}

// ---------------------------------------------------------------------------
// score kernel: m-tile 128, A (fp16) resident across full K via cp.async,
// 5 o-parts x 5 k-chunks, double-buffered 64x64 B.
// 4 warps (128 threads), warp tile m32 x n64. (unchanged from R14)
// ---------------------------------------------------------------------------
#define ACHUNK (128 * 144)               // 18432
#define SM_A 0
#define SM_B (5 * ACHUNK)                // 92160
#define SVS  (SM_B + 2 * 9216)           // 110592
#define SMEM_SCORE (SVS + 320 * 4)       // 111872

__device__ __forceinline__ void stage_B(uint32_t sb, int buf, int ot, int kc)
{
    const int tid = threadIdx.x;
    const uint32_t base = sb + SM_B + (uint32_t)buf * 9216;
#pragma unroll
    for (int q = 0; q < 4; q++) {        // 512 segs / 128 thr
        int it = tid + q * 128;
        int r = it >> 3, s = it & 7;
        cp_async16(base + (uint32_t)(r * 144 + s * 16),
                   g_Ws + (size_t)(ot * 64 + r) * DPAD + kc * 64 + s * 8);
    }
    CP_COMMIT();
}

__global__ __launch_bounds__(128, 2)
void score_mma_kernel(const float* __restrict__ v)
{
    extern __shared__ char smem[];
    const uint32_t sb = smem_u32(smem);
    const int tid = threadIdx.x;
    const int wid = tid >> 5, lid = tid & 31;
    const int m0 = blockIdx.x * 128;
    const int wm = wid * 32;

    float* vsm = (float*)(smem + SVS);   // [320], zero-padded

    // Prologue: stage ALL A chunks (once, fp16 from g_seqh) + B(0,0)
    {
#pragma unroll
        for (int q = 0; q < 40; q++) {   // 5*1024 segs / 128 thr
            int it = tid + q * 128;
            int kc = it >> 10;
            int w = it & 1023;
            int r = w >> 3, s = w & 7;
            cp_async16(sb + SM_A + (uint32_t)(kc * ACHUNK + r * 144 + s * 16),
                       g_seqh + (size_t)(m0 + r) * DPAD + kc * 64 + s * 8);
        }
        stage_B(sb, 0, 0, 0);            // commits A+B together
    }

    for (int it = tid; it < 320; it += 128)
        vsm[it] = (it < D) ? v[it] : 0.f;

    CP_WAIT0();
    __syncthreads();

    // ldmatrix lane addressing
    const int a_row = ((lid >> 3) & 1) * 8 + (lid & 7);
    const int a_col = (lid >> 4) * 8;
    const int b_row = (lid >> 4) * 8 + (lid & 7);
    const int b_col = ((lid >> 3) & 1) * 8;
    const uint32_t aAoff = (uint32_t)((wm + a_row) * 144 + a_col * 2);
    const uint32_t aBoff = (uint32_t)(b_row * 144 + b_col * 2);

    const int g = lid >> 2, t = lid & 3;
    int rr[4];
    rr[0] = wm + g;      rr[1] = wm + 8 + g;
    rr[2] = wm + 16 + g; rr[3] = wm + 24 + g;
    const float* vp[4];
#pragma unroll
    for (int q = 0; q < 4; q++)
        vp[q] = g_vecpart + (size_t)((m0 + rr[q]) / WL) * D;

    float p[4] = {0.f, 0.f, 0.f, 0.f};
    float acc0[8][4], acc1[8][4];

    for (int i = 0; i < 25; i++) {
        const int ot = i / 5, kc = i - ot * 5, buf = i & 1;

        if (kc == 0) {
#pragma unroll
            for (int j = 0; j < 8; j++)
#pragma unroll
                for (int q = 0; q < 4; q++) { acc0[j][q] = 0.f; acc1[j][q] = 0.f; }
        }

        if (i + 1 < 25) {
            int ni = i + 1, not_ = ni / 5, nkc = ni - not_ * 5;
            stage_B(sb, ni & 1, not_, nkc);
        }

        const uint32_t abase = sb + SM_A + (uint32_t)kc * ACHUNK;
        const uint32_t bbase = sb + SM_B + (uint32_t)buf * 9216;
#pragma unroll
        for (int ks = 0; ks < 4; ks++) {
            const uint32_t kb = (uint32_t)ks * 32;
            uint32_t a0[4], a1[4];
            ldsm_x4(a0, abase + aAoff + kb);
            ldsm_x4(a1, abase + aAoff + kb + 16 * 144);
#pragma unroll
            for (int pp = 0; pp < 4; pp++) {
                uint32_t b[4];
                ldsm_x4(b, bbase + aBoff + kb + (uint32_t)(pp * 16 * 144));
                mma_f16(acc0[2*pp],   a0, b);
                mma_f16(acc0[2*pp+1], a0, b + 2);
                mma_f16(acc1[2*pp],   a1, b);
                mma_f16(acc1[2*pp+1], a1, b + 2);
            }
        }

        // End of o-part: tanh(lin)*v (branch-free: padded o terms are 0)
        if (kc == 4) {
            const int o0 = ot * 64;
#pragma unroll
            for (int j = 0; j < 8; j++) {
                int o = o0 + j * 8 + 2 * t;
                float v0 = vsm[o], v1 = vsm[o + 1];
                p[0] += tanh_fast(acc0[j][0] + __ldg(vp[0] + o)) * v0
                      + tanh_fast(acc0[j][1] + __ldg(vp[0] + o + 1)) * v1;
                p[1] += tanh_fast(acc0[j][2] + __ldg(vp[1] + o)) * v0
                      + tanh_fast(acc0[j][3] + __ldg(vp[1] + o + 1)) * v1;
                p[2] += tanh_fast(acc1[j][0] + __ldg(vp[2] + o)) * v0
                      + tanh_fast(acc1[j][1] + __ldg(vp[2] + o + 1)) * v1;
                p[3] += tanh_fast(acc1[j][2] + __ldg(vp[3] + o)) * v0
                      + tanh_fast(acc1[j][3] + __ldg(vp[3] + o + 1)) * v1;
            }
        }

        CP_WAIT0();
        __syncthreads();
    }

#pragma unroll
    for (int q = 0; q < 4; q++) {
        p[q] += __shfl_xor_sync(0xffffffffu, p[q], 1);
        p[q] += __shfl_xor_sync(0xffffffffu, p[q], 2);
    }
    if (t == 0) {
#pragma unroll
        for (int q = 0; q < 4; q++)
            g_score[m0 + rr[q]] = p[q];
    }
}

// ---------------------------------------------------------------------------
// vecpart via fp16 HMMA, single-stage (unchanged from R14).
// grid = (64, 5): m-tiles of 64, 4 warps (m16). smem 92416 -> 2 CTAs/SM.
// ---------------------------------------------------------------------------
#define VCHUNK (64 * 144)                // 9216
#define VSM_A 0                          // 5 chunks = 46080
#define VSM_B (5 * VCHUNK)               // 46080
#define VSM_BIAS (2 * 5 * VCHUNK)        // 92160
#define SMEM_VECP (VSM_BIAS + 256)       // 92416

__global__ __launch_bounds__(128, 2)
void vecpart_mma_kernel(const float* __restrict__ bias)
{
    extern __shared__ char smem[];
    const uint32_t sb = smem_u32(smem);
    const int tid = threadIdx.x;
    const int wid = tid >> 5, lid = tid & 31;
    const int m0 = blockIdx.x * 64;
    const int o0 = blockIdx.y * 64;
    const int wm = wid * 16;

    float* bsm = (float*)(smem + VSM_BIAS);

#pragma unroll
    for (int q = 0; q < 20; q++) {
        int it = tid + q * 128;
        int kc = it >> 9;
        int w = it & 511;
        int r = w >> 3, s = w & 7;
        cp_async16(sb + VSM_A + (uint32_t)(kc * VCHUNK + r * 144 + s * 16),
                   g_vech + (size_t)(m0 + r) * DPAD + kc * 64 + s * 8);
        cp_async16(sb + VSM_B + (uint32_t)(kc * VCHUNK + r * 144 + s * 16),
                   g_Wv + (size_t)(o0 + r) * DPAD + kc * 64 + s * 8);
    }
    CP_COMMIT();

    if (tid < 64) bsm[tid] = (o0 + tid < D) ? bias[o0 + tid] : 0.f;

    CP_WAIT0();
    __syncthreads();

    const int a_row = ((lid >> 3) & 1) * 8 + (lid & 7);
    const int a_col = (lid >> 4) * 8;
    const int b_row = (lid >> 4) * 8 + (lid & 7);
    const int b_col = ((lid >> 3) & 1) * 8;
    const uint32_t aAoff = (uint32_t)((wm + a_row) * 144 + a_col * 2);
    const uint32_t aBoff = (uint32_t)(b_row * 144 + b_col * 2);

    const int g = lid >> 2, t = lid & 3;
    const int r0 = wm + g, r1 = wm + 8 + g;

    float acc[8][4];
#pragma unroll
    for (int j = 0; j < 8; j++)
#pragma unroll
        for (int q = 0; q < 4; q++) acc[j][q] = 0.f;

#pragma unroll
    for (int kc = 0; kc < 5; kc++) {
        const uint32_t abase = sb + VSM_A + (uint32_t)kc * VCHUNK;
        const uint32_t bbase = sb + VSM_B + (uint32_t)kc * VCHUNK;
#pragma unroll
        for (int ks = 0; ks < 4; ks++) {
            const uint32_t kb = (uint32_t)ks * 32;
            uint32_t a0[4];
            ldsm_x4(a0, abase + aAoff + kb);
#pragma unroll
            for (int pp = 0; pp < 4; pp++) {
                uint32_t b[4];
                ldsm_x4(b, bbase + aBoff + kb + (uint32_t)(pp * 16 * 144));
                mma_f16(acc[2*pp],   a0, b);
                mma_f16(acc[2*pp+1], a0, b + 2);
            }
        }
    }

#pragma unroll
    for (int j = 0; j < 8; j++) {
        int oc = j * 8 + 2 * t;
        int o = o0 + oc;
        if (o < D) {
            float bb = bsm[oc];
            g_vecpart[(size_t)(m0 + r0) * D + o] = acc[j][0] + bb;
            g_vecpart[(size_t)(m0 + r1) * D + o] = acc[j][2] + bb;
        }
        if (o + 1 < D) {
            float bb = bsm[oc + 1];
            g_vecpart[(size_t)(m0 + r0) * D + o + 1] = acc[j][1] + bb;
            g_vecpart[(size_t)(m0 + r1) * D + o + 1] = acc[j][3] + bb;
        }
    }
}

// ---------------------------------------------------------------------------
// softmax+weighted: ONE WARP per (b,s), fp16 seq (unchanged from R14).
// ---------------------------------------------------------------------------
__global__ __launch_bounds__(256)
void softmax_weighted_kernel(const int* __restrict__ masks,
                             float* __restrict__ out)
{
    const int warp = threadIdx.x >> 5, lid = threadIdx.x & 31;
    const int bs = blockIdx.x * 8 + warp;

    float s = -1e30f;
    if (lid < WL) {
        s = g_score[bs * WL + lid];
        if (masks[bs * WL + lid] == 0) s = NEG_INF;
    }
    float mx = s;
#pragma unroll
    for (int off = 16; off > 0; off >>= 1)
        mx = fmaxf(mx, __shfl_xor_sync(0xffffffffu, mx, off));
    float e = (lid < WL) ? expf(s - mx) : 0.f;
    float sum = e;
#pragma unroll
    for (int off = 16; off > 0; off >>= 1)
        sum += __shfl_xor_sync(0xffffffffu, sum, off);
    const float inv = 1.f / sum;

    float al[WL];
#pragma unroll
    for (int w = 0; w < WL; w++)
        al[w] = __shfl_sync(0xffffffffu, e, w) * inv;

    const __half* base = g_seqh + (size_t)bs * WL * DPAD;
    float* obase = out + (size_t)bs * D;
    for (int d2 = lid; d2 < D / 2; d2 += 32) {
        float a0 = 0.f, a1 = 0.f;
#pragma unroll
        for (int w = 0; w < WL; w++) {
            float2 x = __half22float2(*(const __half2*)(base + w * DPAD + d2 * 2));
            a0 += al[w] * x.x;
            a1 += al[w] * x.y;
        }
        obase[d2 * 2]     = a0;
        obase[d2 * 2 + 1] = a1;
    }
}

// ---------------------------------------------------------------------------
extern "C" void kernel_launch(void* const* d_in, const int* in_sizes, int n_in,
                              void* d_out, int out_size)
{
    const float* seq   = (const float*)d_in[0];
    const float* vec   = (const float*)d_in[1];
    const int*   masks = (const int*)  d_in[2];
    const float* W     = (const float*)d_in[3];
    const float* bias  = (const float*)d_in[4];
    const float* v     = (const float*)d_in[5];
    float* out = (float*)d_out;

    cudaFuncSetAttribute(score_mma_kernel,
                         cudaFuncAttributeMaxDynamicSharedMemorySize, SMEM_SCORE);
    cudaFuncSetAttribute(vecpart_mma_kernel,
                         cudaFuncAttributeMaxDynamicSharedMemorySize, SMEM_VECP);

    prep_w_kernel<<<(DPAD * DPAD + 255) / 256, 256>>>(W);
    prep_seq_kernel<<<M_SEQ * 8 / 256, 256>>>(seq);
    prep_vec_kernel<<<M_VEC * 8 / 256, 256>>>(vec);
    vecpart_mma_kernel<<<dim3(M_VEC / 64, 5), 128, SMEM_VECP>>>(bias);
    score_mma_kernel<<<M_SEQ / 128, 128, SMEM_SCORE>>>(v);
    softmax_weighted_kernel<<<M_VEC / 8, 256>>>(masks, out);
}

// round 17
// speedup vs baseline: 1.1812x; 1.0724x over previous
#include <cuda_runtime.h>
#include <cuda_fp16.h>
#include <math.h>
#include <stdint.h>

// Problem constants
#define BATCH 32
#define SEQ   128
#define WL    20
#define D     300
#define DPAD  320
#define M_SEQ (BATCH*SEQ*WL)      // 81920
#define M_VEC (BATCH*SEQ)         // 4096
#define NEG_INF -1000000000.0f

// Scratch (__device__ globals — no cudaMalloc allowed)
// +64 pad: score epilogue reads vecpart rows with o up to 319.
__device__ float g_vecpart[M_VEC * D + 64];
__device__ float g_score[M_SEQ];
__device__ __align__(16) __half g_Ws[DPAD * DPAD];
__device__ __align__(16) __half g_Wv[DPAD * DPAD];
__device__ __align__(16) __half g_seqh[(size_t)M_SEQ * DPAD];
__device__ __align__(16) __half g_vech[(size_t)M_VEC * DPAD];

// ---------------------------------------------------------------------------
// PTX helpers (sm_80-era — valid at plain sm_103 target)
// ---------------------------------------------------------------------------
__device__ __forceinline__ uint32_t smem_u32(const void* p) {
    uint32_t a;
    asm("{ .reg .u64 t; cvta.to.shared.u64 t, %1; cvt.u32.u64 %0, t; }" : "=r"(a) : "l"(p));
    return a;
}
__device__ __forceinline__ void ldsm_x4(uint32_t* r, uint32_t addr) {
    asm volatile("ldmatrix.sync.aligned.m8n8.x4.shared.b16 {%0,%1,%2,%3}, [%4];"
                 : "=r"(r[0]), "=r"(r[1]), "=r"(r[2]), "=r"(r[3]) : "r"(addr));
}
__device__ __forceinline__ void mma_f16(float* c, const uint32_t* a, const uint32_t* b) {
    asm volatile("mma.sync.aligned.m16n8k16.row.col.f32.f16.f16.f32 "
                 "{%0,%1,%2,%3}, {%4,%5,%6,%7}, {%8,%9}, {%0,%1,%2,%3};"
                 : "+f"(c[0]), "+f"(c[1]), "+f"(c[2]), "+f"(c[3])
                 : "r"(a[0]), "r"(a[1]), "r"(a[2]), "r"(a[3]), "r"(b[0]), "r"(b[1]));
}
__device__ __forceinline__ void cp_async16(uint32_t dst, const void* src) {
    asm volatile("cp.async.cg.shared.global [%0], [%1], 16;"
                 :: "r"(dst), "l"((size_t)__cvta_generic_to_global(src)) : "memory");
}
#define CP_COMMIT() asm volatile("cp.async.commit_group;" ::: "memory")
#define CP_WAIT0()  asm volatile("cp.async.wait_group 0;" ::: "memory")
#define CP_WAIT1()  asm volatile("cp.async.wait_group 1;" ::: "memory")

__device__ __forceinline__ float tanh_fast(float x) {
    float y;
    asm("tanh.approx.f32 %0, %1;" : "=f"(y) : "f"(x));
    return y;
}

// ---------------------------------------------------------------------------
// Prep kernels: fp16 conversion with zero padding (16B stores) — R14 versions
// (coalesced: consecutive threads handle consecutive k8 groups)
// ---------------------------------------------------------------------------
__device__ __forceinline__ void cvt8_store(__half* dst, const float* src, int k8) {
    uint4 out;
    __half2 h[4];
    if (k8 < 37) {
        float4 a = *(const float4*)(src);
        float4 b = *(const float4*)(src + 4);
        h[0] = __floats2half2_rn(a.x, a.y);
        h[1] = __floats2half2_rn(a.z, a.w);
        h[2] = __floats2half2_rn(b.x, b.y);
        h[3] = __floats2half2_rn(b.z, b.w);
    } else if (k8 == 37) {
        float4 a = *(const float4*)(src);
        h[0] = __floats2half2_rn(a.x, a.y);
        h[1] = __floats2half2_rn(a.z, a.w);
        h[2] = __floats2half2_rn(0.f, 0.f);
        h[3] = h[2];
    } else {
        h[0] = __floats2half2_rn(0.f, 0.f);
        h[1] = h[0]; h[2] = h[0]; h[3] = h[0];
    }
    memcpy(&out, h, 16);
    *(uint4*)dst = out;
}

__global__ __launch_bounds__(256)
void prep_seq_kernel(const float* __restrict__ seq)
{
    size_t gid = (size_t)blockIdx.x * 256 + threadIdx.x;
    if (gid >= (size_t)M_SEQ * (DPAD / 8)) return;
    size_t row = gid / (DPAD / 8);
    int k8 = (int)(gid % (DPAD / 8));
    cvt8_store(g_seqh + row * DPAD + k8 * 8, seq + row * D + (size_t)k8 * 8, k8);
}

__global__ __launch_bounds__(256)
void prep_vec_kernel(const float* __restrict__ vec)
{
    size_t gid = (size_t)blockIdx.x * 256 + threadIdx.x;
    if (gid >= (size_t)M_VEC * (DPAD / 8)) return;
    size_t row = gid / (DPAD / 8);
    int k8 = (int)(gid % (DPAD / 8));
    cvt8_store(g_vech + row * DPAD + k8 * 8, vec + row * D + (size_t)k8 * 8, k8);
}

__global__ __launch_bounds__(256)
void prep_w_kernel(const float* __restrict__ W)
{
    int idx = blockIdx.x * 256 + threadIdx.x;
    if (idx >= DPAD * DPAD) return;
    int o = idx / DPAD, k = idx - o * DPAD;
    float ws = 0.f, wv = 0.f;
    if (o < D && k < D) {
        ws = W[(size_t)o * 600 + k];
        wv = W[(size_t)o * 600 + 300 + k];
    }
    g_Ws[idx] = __float2half_rn(ws);
    g_Wv[idx] = __float2half_rn(wv);
}

// ---------------------------------------------------------------------------
// score kernel: m-tile 128, A (fp16) resident across full K via cp.async,
// 5 o-parts x 5 k-chunks, double-buffered 64x64 B.
// 4 warps (128 threads), warp tile m32 x n64.
// Prologue split: A chunks 0-1 + B(0,0) exposed; A chunks 2-4 overlap iter 0.
// smem = 92160 + 18432 + 1280 = 111872 (2 CTAs/SM).
// ---------------------------------------------------------------------------
#define ACHUNK (128 * 144)               // 18432
#define SM_A 0
#define SM_B (5 * ACHUNK)                // 92160
#define SVS  (SM_B + 2 * 9216)           // 110592
#define SMEM_SCORE (SVS + 320 * 4)       // 111872

__device__ __forceinline__ void stage_B(uint32_t sb, int buf, int ot, int kc)
{
    const int tid = threadIdx.x;
    const uint32_t base = sb + SM_B + (uint32_t)buf * 9216;
#pragma unroll
    for (int q = 0; q < 4; q++) {        // 512 segs / 128 thr
        int it = tid + q * 128;
        int r = it >> 3, s = it & 7;
        cp_async16(base + (uint32_t)(r * 144 + s * 16),
                   g_Ws + (size_t)(ot * 64 + r) * DPAD + kc * 64 + s * 8);
    }
    CP_COMMIT();
}

// Stage A chunks [c0, c1) from g_seqh (1024 16B segs per chunk, 128 threads)
__device__ __forceinline__ void stage_A_chunks(uint32_t sb, int m0, int c0, int c1)
{
    const int tid = threadIdx.x;
    for (int kc = c0; kc < c1; kc++) {
#pragma unroll
        for (int q = 0; q < 8; q++) {
            int it = tid + q * 128;
            int r = it >> 3, s = it & 7;
            cp_async16(sb + SM_A + (uint32_t)(kc * ACHUNK + r * 144 + s * 16),
                       g_seqh + (size_t)(m0 + r) * DPAD + kc * 64 + s * 8);
        }
    }
}

__global__ __launch_bounds__(128, 2)
void score_mma_kernel(const float* __restrict__ v)
{
    extern __shared__ char smem[];
    const uint32_t sb = smem_u32(smem);
    const int tid = threadIdx.x;
    const int wid = tid >> 5, lid = tid & 31;
    const int m0 = blockIdx.x * 128;
    const int wm = wid * 32;

    float* vsm = (float*)(smem + SVS);   // [320], zero-padded

    // Prologue group 1: A chunks 0-1 + B(0,0) (exposed wait)
    stage_A_chunks(sb, m0, 0, 2);
    stage_B(sb, 0, 0, 0);                // commits group 1
    // Prologue group 2: A chunks 2-4 (drains during iteration 0)
    stage_A_chunks(sb, m0, 2, 5);
    CP_COMMIT();

    for (int it = tid; it < 320; it += 128)
        vsm[it] = (it < D) ? v[it] : 0.f;

    CP_WAIT1();                          // group 1 done; group 2 in flight
    __syncthreads();

    // ldmatrix lane addressing
    const int a_row = ((lid >> 3) & 1) * 8 + (lid & 7);
    const int a_col = (lid >> 4) * 8;
    const int b_row = (lid >> 4) * 8 + (lid & 7);
    const int b_col = ((lid >> 3) & 1) * 8;
    const uint32_t aAoff = (uint32_t)((wm + a_row) * 144 + a_col * 2);
    const uint32_t aBoff = (uint32_t)(b_row * 144 + b_col * 2);

    const int g = lid >> 2, t = lid & 3;
    int rr[4];
    rr[0] = wm + g;      rr[1] = wm + 8 + g;
    rr[2] = wm + 16 + g; rr[3] = wm + 24 + g;
    const float* vp[4];
#pragma unroll
    for (int q = 0; q < 4; q++)
        vp[q] = g_vecpart + (size_t)((m0 + rr[q]) / WL) * D;

    float p[4] = {0.f, 0.f, 0.f, 0.f};
    float acc0[8][4], acc1[8][4];

    for (int i = 0; i < 25; i++) {
        const int ot = i / 5, kc = i - ot * 5, buf = i & 1;

        if (kc == 0) {
#pragma unroll
            for (int j = 0; j < 8; j++)
#pragma unroll
                for (int q = 0; q < 4; q++) { acc0[j][q] = 0.f; acc1[j][q] = 0.f; }
        }

        if (i + 1 < 25) {
            int ni = i + 1, not_ = ni / 5, nkc = ni - not_ * 5;
            stage_B(sb, ni & 1, not_, nkc);
        }

        const uint32_t abase = sb + SM_A + (uint32_t)kc * ACHUNK;
        const uint32_t bbase = sb + SM_B + (uint32_t)buf * 9216;
#pragma unroll
        for (int ks = 0; ks < 4; ks++) {
            const uint32_t kb = (uint32_t)ks * 32;
            uint32_t a0[4], a1[4];
            ldsm_x4(a0, abase + aAoff + kb);
            ldsm_x4(a1, abase + aAoff + kb + 16 * 144);
#pragma unroll
            for (int pp = 0; pp < 4; pp++) {
                uint32_t b[4];
                ldsm_x4(b, bbase + aBoff + kb + (uint32_t)(pp * 16 * 144));
                mma_f16(acc0[2*pp],   a0, b);
                mma_f16(acc0[2*pp+1], a0, b + 2);
                mma_f16(acc1[2*pp],   a1, b);
                mma_f16(acc1[2*pp+1], a1, b + 2);
            }
        }

        // End of o-part: tanh(lin)*v (branch-free: padded o terms are 0)
        if (kc == 4) {
            const int o0 = ot * 64;
#pragma unroll
            for (int j = 0; j < 8; j++) {
                int o = o0 + j * 8 + 2 * t;
                float v0 = vsm[o], v1 = vsm[o + 1];
                p[0] += tanh_fast(acc0[j][0] + __ldg(vp[0] + o)) * v0
                      + tanh_fast(acc0[j][1] + __ldg(vp[0] + o + 1)) * v1;
                p[1] += tanh_fast(acc0[j][2] + __ldg(vp[1] + o)) * v0
                      + tanh_fast(acc0[j][3] + __ldg(vp[1] + o + 1)) * v1;
                p[2] += tanh_fast(acc1[j][0] + __ldg(vp[2] + o)) * v0
                      + tanh_fast(acc1[j][1] + __ldg(vp[2] + o + 1)) * v1;
                p[3] += tanh_fast(acc1[j][2] + __ldg(vp[3] + o)) * v0
                      + tanh_fast(acc1[j][3] + __ldg(vp[3] + o + 1)) * v1;
            }
        }

        CP_WAIT0();                      // drains next-B (and, at i=0, A chunks 2-4)
        __syncthreads();
    }

#pragma unroll
    for (int q = 0; q < 4; q++) {
        p[q] += __shfl_xor_sync(0xffffffffu, p[q], 1);
        p[q] += __shfl_xor_sync(0xffffffffu, p[q], 2);
    }
    if (t == 0) {
#pragma unroll
        for (int q = 0; q < 4; q++)
            g_score[m0 + rr[q]] = p[q];
    }
}

// ---------------------------------------------------------------------------
// vecpart via fp16 HMMA, two-phase staging: kc 0-1 exposed, kc 2-4 overlap.
// grid = (64, 5): m-tiles of 64, 4 warps (m16). smem 92416 -> 2 CTAs/SM.
// ---------------------------------------------------------------------------
#define VCHUNK (64 * 144)                // 9216
#define VSM_A 0                          // 5 chunks = 46080
#define VSM_B (5 * VCHUNK)               // 46080
#define VSM_BIAS (2 * 5 * VCHUNK)        // 92160
#define SMEM_VECP (VSM_BIAS + 256)       // 92416

// Stage A (g_vech) + B (g_Wv) for k-chunks [c0, c1); 512 segs per chunk pair.
__device__ __forceinline__ void vstage_chunks(uint32_t sb, int m0, int o0,
                                              int c0, int c1)
{
    const int tid = threadIdx.x;
    for (int kc = c0; kc < c1; kc++) {
#pragma unroll
        for (int q = 0; q < 4; q++) {
            int it = tid + q * 128;
            int r = it >> 3, s = it & 7;
            cp_async16(sb + VSM_A + (uint32_t)(kc * VCHUNK + r * 144 + s * 16),
                       g_vech + (size_t)(m0 + r) * DPAD + kc * 64 + s * 8);
            cp_async16(sb + VSM_B + (uint32_t)(kc * VCHUNK + r * 144 + s * 16),
                       g_Wv + (size_t)(o0 + r) * DPAD + kc * 64 + s * 8);
        }
    }
}

__global__ __launch_bounds__(128, 2)
void vecpart_mma_kernel(const float* __restrict__ bias)
{
    extern __shared__ char smem[];
    const uint32_t sb = smem_u32(smem);
    const int tid = threadIdx.x;
    const int wid = tid >> 5, lid = tid & 31;
    const int m0 = blockIdx.x * 64;
    const int o0 = blockIdx.y * 64;
    const int wm = wid * 16;

    float* bsm = (float*)(smem + VSM_BIAS);

    // Group 1: kc 0-1 (exposed); Group 2: kc 2-4 (overlaps kc 0-1 compute)
    vstage_chunks(sb, m0, o0, 0, 2);
    CP_COMMIT();
    vstage_chunks(sb, m0, o0, 2, 5);
    CP_COMMIT();

    if (tid < 64) bsm[tid] = (o0 + tid < D) ? bias[o0 + tid] : 0.f;

    CP_WAIT1();                          // kc 0-1 ready
    __syncthreads();

    const int a_row = ((lid >> 3) & 1) * 8 + (lid & 7);
    const int a_col = (lid >> 4) * 8;
    const int b_row = (lid >> 4) * 8 + (lid & 7);
    const int b_col = ((lid >> 3) & 1) * 8;
    const uint32_t aAoff = (uint32_t)((wm + a_row) * 144 + a_col * 2);
    const uint32_t aBoff = (uint32_t)(b_row * 144 + b_col * 2);

    const int g = lid >> 2, t = lid & 3;
    const int r0 = wm + g, r1 = wm + 8 + g;

    float acc[8][4];
#pragma unroll
    for (int j = 0; j < 8; j++)
#pragma unroll
        for (int q = 0; q < 4; q++) acc[j][q] = 0.f;

    // Phase 1: kc 0-1
#pragma unroll
    for (int kc = 0; kc < 2; kc++) {
        const uint32_t abase = sb + VSM_A + (uint32_t)kc * VCHUNK;
        const uint32_t bbase = sb + VSM_B + (uint32_t)kc * VCHUNK;
#pragma unroll
        for (int ks = 0; ks < 4; ks++) {
            const uint32_t kb = (uint32_t)ks * 32;
            uint32_t a0[4];
            ldsm_x4(a0, abase + aAoff + kb);
#pragma unroll
            for (int pp = 0; pp < 4; pp++) {
                uint32_t b[4];
                ldsm_x4(b, bbase + aBoff + kb + (uint32_t)(pp * 16 * 144));
                mma_f16(acc[2*pp],   a0, b);
                mma_f16(acc[2*pp+1], a0, b + 2);
            }
        }
    }

    CP_WAIT0();                          // kc 2-4 ready (overlapped with above)
    __syncthreads();

    // Phase 2: kc 2-4
#pragma unroll
    for (int kc = 2; kc < 5; kc++) {
        const uint32_t abase = sb + VSM_A + (uint32_t)kc * VCHUNK;
        const uint32_t bbase = sb + VSM_B + (uint32_t)kc * VCHUNK;
#pragma unroll
        for (int ks = 0; ks < 4; ks++) {
            const uint32_t kb = (uint32_t)ks * 32;
            uint32_t a0[4];
            ldsm_x4(a0, abase + aAoff + kb);
#pragma unroll
            for (int pp = 0; pp < 4; pp++) {
                uint32_t b[4];
                ldsm_x4(b, bbase + aBoff + kb + (uint32_t)(pp * 16 * 144));
                mma_f16(acc[2*pp],   a0, b);
                mma_f16(acc[2*pp+1], a0, b + 2);
            }
        }
    }

#pragma unroll
    for (int j = 0; j < 8; j++) {
        int oc = j * 8 + 2 * t;
        int o = o0 + oc;
        if (o < D) {
            float bb = bsm[oc];
            g_vecpart[(size_t)(m0 + r0) * D + o] = acc[j][0] + bb;
            g_vecpart[(size_t)(m0 + r1) * D + o] = acc[j][2] + bb;
        }
        if (o + 1 < D) {
            float bb = bsm[oc + 1];
            g_vecpart[(size_t)(m0 + r0) * D + o + 1] = acc[j][1] + bb;
            g_vecpart[(size_t)(m0 + r1) * D + o + 1] = acc[j][3] + bb;
        }
    }
}

// ---------------------------------------------------------------------------
// softmax+weighted: ONE WARP per (b,s), fp16 seq (unchanged from R14).
// ---------------------------------------------------------------------------
__global__ __launch_bounds__(256)
void softmax_weighted_kernel(const int* __restrict__ masks,
                             float* __restrict__ out)
{
    const int warp = threadIdx.x >> 5, lid = threadIdx.x & 31;
    const int bs = blockIdx.x * 8 + warp;

    float s = -1e30f;
    if (lid < WL) {
        s = g_score[bs * WL + lid];
        if (masks[bs * WL + lid] == 0) s = NEG_INF;
    }
    float mx = s;
#pragma unroll
    for (int off = 16; off > 0; off >>= 1)
        mx = fmaxf(mx, __shfl_xor_sync(0xffffffffu, mx, off));
    float e = (lid < WL) ? expf(s - mx) : 0.f;
    float sum = e;
#pragma unroll
    for (int off = 16; off > 0; off >>= 1)
        sum += __shfl_xor_sync(0xffffffffu, sum, off);
    const float inv = 1.f / sum;

    float al[WL];
#pragma unroll
    for (int w = 0; w < WL; w++)
        al[w] = __shfl_sync(0xffffffffu, e, w) * inv;

    const __half* base = g_seqh + (size_t)bs * WL * DPAD;
    float* obase = out + (size_t)bs * D;
    for (int d2 = lid; d2 < D / 2; d2 += 32) {
        float a0 = 0.f, a1 = 0.f;
#pragma unroll
        for (int w = 0; w < WL; w++) {
            float2 x = __half22float2(*(const __half2*)(base + w * DPAD + d2 * 2));
            a0 += al[w] * x.x;
            a1 += al[w] * x.y;
        }
        obase[d2 * 2]     = a0;
        obase[d2 * 2 + 1] = a1;
    }
}

// ---------------------------------------------------------------------------
extern "C" void kernel_launch(void* const* d_in, const int* in_sizes, int n_in,
                              void* d_out, int out_size)
{
    const float* seq   = (const float*)d_in[0];
    const float* vec   = (const float*)d_in[1];
    const int*   masks = (const int*)  d_in[2];
    const float* W     = (const float*)d_in[3];
    const float* bias  = (const float*)d_in[4];
    const float* v     = (const float*)d_in[5];
    float* out = (float*)d_out;

    cudaFuncSetAttribute(score_mma_kernel,
                         cudaFuncAttributeMaxDynamicSharedMemorySize, SMEM_SCORE);
    cudaFuncSetAttribute(vecpart_mma_kernel,
                         cudaFuncAttributeMaxDynamicSharedMemorySize, SMEM_VECP);

    prep_w_kernel<<<(DPAD * DPAD + 255) / 256, 256>>>(W);
    prep_seq_kernel<<<(int)(((size_t)M_SEQ * (DPAD / 8) + 255) / 256), 256>>>(seq);
    prep_vec_kernel<<<(int)(((size_t)M_VEC * (DPAD / 8) + 255) / 256), 256>>>(vec);
    vecpart_mma_kernel<<<dim3(M_VEC / 64, 5), 128, SMEM_VECP>>>(bias);
    score_mma_kernel<<<M_SEQ / 128, 128, SMEM_SCORE>>>(v);
    softmax_weighted_kernel<<<M_VEC / 8, 256>>>(masks, out);
}